// round 2
// baseline (speedup 1.0000x reference)
#include <cuda_runtime.h>
#include <cuda_bf16.h>

#define NN 50000
#define EE 800000
#define DD 128

// ---------------- scratch (no allocations allowed) ----------------
__device__ int   g_degi[NN];
__device__ float g_dinv[NN];
__device__ float g_bufA[NN * DD];   // gemm output / scatter input
__device__ float g_bufB[NN * DD];   // relu output (gemm2 input)
__device__ float g_agg [NN * DD];   // aggregation accumulator

// ---------------- degree / normalization ----------------
__global__ void k_init_deg() {
    int i = blockIdx.x * blockDim.x + threadIdx.x;
    if (i < NN) g_degi[i] = 1;   // self-loop
}

__global__ void k_count_deg(const int* __restrict__ dst) {
    int e = blockIdx.x * blockDim.x + threadIdx.x;
    if (e < EE) atomicAdd(&g_degi[dst[e]], 1);
}

__global__ void k_dinv() {
    int i = blockIdx.x * blockDim.x + threadIdx.x;
    if (i < NN) g_dinv[i] = rsqrtf((float)g_degi[i]);
}

// ---------------- GEMM: Y[M,128] = X[M,128] @ W[128,128] ----------------
// 256 threads/block, 64-row x 128-col tile, 8x4 micro-tile per thread.
// k-dim processed in two 64-wide halves to stay within 48KB static smem.
__global__ void k_gemm(const float* __restrict__ X, const float* __restrict__ W,
                       float* __restrict__ Y, int M) {
    __shared__ float sW[64 * 128];   // 32KB: [k][c]
    __shared__ float sX[64 * 64];    // 16KB: [r][k]

    int tid  = threadIdx.x;
    int row0 = blockIdx.x * 64;
    int nrows = M - row0; if (nrows > 64) nrows = 64;

    int tc = tid & 31;   // cols tc*4 .. tc*4+3
    int tr = tid >> 5;   // rows tr*8 .. tr*8+7

    float acc[8][4];
#pragma unroll
    for (int r = 0; r < 8; r++)
#pragma unroll
        for (int j = 0; j < 4; j++) acc[r][j] = 0.f;

    const float4* W4 = (const float4*)W;
    const float4* X4 = (const float4*)X;

    for (int kk = 0; kk < 128; kk += 64) {
        // load W[kk..kk+64][0..128): 64*32 float4
        for (int i = tid; i < 64 * 32; i += 256) {
            int k  = i >> 5;
            int c4 = i & 31;
            ((float4*)sW)[i] = W4[(kk + k) * 32 + c4];
        }
        // load X[row0..row0+64][kk..kk+64): 64*16 float4
        for (int i = tid; i < 64 * 16; i += 256) {
            int r  = i >> 4;
            int c4 = i & 15;
            float4 v = make_float4(0.f, 0.f, 0.f, 0.f);
            if (r < nrows) v = X4[(size_t)(row0 + r) * 32 + (kk >> 2) + c4];
            ((float4*)sX)[i] = v;
        }
        __syncthreads();

#pragma unroll 8
        for (int k = 0; k < 64; k++) {
            float4 w = ((float4*)sW)[k * 32 + tc];
            float xr[8];
#pragma unroll
            for (int r = 0; r < 8; r++) xr[r] = sX[(tr * 8 + r) * 64 + k];
#pragma unroll
            for (int r = 0; r < 8; r++) {
                acc[r][0] += xr[r] * w.x;
                acc[r][1] += xr[r] * w.y;
                acc[r][2] += xr[r] * w.z;
                acc[r][3] += xr[r] * w.w;
            }
        }
        __syncthreads();
    }

#pragma unroll
    for (int r = 0; r < 8; r++) {
        int row = row0 + tr * 8 + r;
        if (row < M) {
            float4 v = make_float4(acc[r][0], acc[r][1], acc[r][2], acc[r][3]);
            ((float4*)(Y + (size_t)row * DD))[tc] = v;
        }
    }
}

// ---------------- self-loop init: agg[i] = H[i] * dinv[i]^2 ----------------
__global__ void k_selfinit(const float* __restrict__ H, float* __restrict__ out) {
    int gid = blockIdx.x * blockDim.x + threadIdx.x;
    int i = gid >> 5;
    if (i >= NN) return;
    int lane = gid & 31;
    float di = g_dinv[i];
    float w = di * di;
    float4 v = ((const float4*)(H + (size_t)i * DD))[lane];
    v.x *= w; v.y *= w; v.z *= w; v.w *= w;
    ((float4*)(out + (size_t)i * DD))[lane] = v;
}

// ---------------- edge scatter: agg[dst] += H[src] * dinv[src]*dinv[dst] ----
// one warp per edge; each lane reduces 4 consecutive floats with red.v4.f32
__global__ void k_scatter(const float* __restrict__ H,
                          const int* __restrict__ src, const int* __restrict__ dst,
                          float* __restrict__ out) {
    int gid = blockIdx.x * blockDim.x + threadIdx.x;
    int e = gid >> 5;
    if (e >= EE) return;
    int lane = gid & 31;
    int s = src[e];
    int d = dst[e];
    float nrm = g_dinv[s] * g_dinv[d];
    float4 v = ((const float4*)(H + (size_t)s * DD))[lane];
    v.x *= nrm; v.y *= nrm; v.z *= nrm; v.w *= nrm;
    float* p = out + (size_t)d * DD + lane * 4;
    asm volatile("red.global.add.v4.f32 [%0], {%1,%2,%3,%4};"
                 :: "l"(p), "f"(v.x), "f"(v.y), "f"(v.z), "f"(v.w)
                 : "memory");
}

// ---------------- bias + relu ----------------
__global__ void k_bias_relu(const float* __restrict__ A, const float* __restrict__ b,
                            float* __restrict__ out) {
    int gid = blockIdx.x * blockDim.x + threadIdx.x;
    int i = gid >> 5;
    if (i >= NN) return;
    int lane = gid & 31;
    float4 v  = ((const float4*)(A + (size_t)i * DD))[lane];
    float4 bb = ((const float4*)b)[lane];
    v.x = fmaxf(v.x + bb.x, 0.f);
    v.y = fmaxf(v.y + bb.y, 0.f);
    v.z = fmaxf(v.z + bb.z, 0.f);
    v.w = fmaxf(v.w + bb.w, 0.f);
    ((float4*)(out + (size_t)i * DD))[lane] = v;
}

// ---------------- heads: relu(agg + b2), then two dot products ----------------
__global__ void k_heads(const float* __restrict__ A, const float* __restrict__ b2,
                        const float* __restrict__ Wt, const float* __restrict__ bt,
                        const float* __restrict__ We, const float* __restrict__ be,
                        float* __restrict__ out) {
    int gid = blockIdx.x * blockDim.x + threadIdx.x;
    int i = gid >> 5;
    if (i >= NN) return;
    int lane = gid & 31;
    float4 v  = ((const float4*)(A + (size_t)i * DD))[lane];
    float4 bb = ((const float4*)b2)[lane];
    v.x = fmaxf(v.x + bb.x, 0.f);
    v.y = fmaxf(v.y + bb.y, 0.f);
    v.z = fmaxf(v.z + bb.z, 0.f);
    v.w = fmaxf(v.w + bb.w, 0.f);
    float4 wt = ((const float4*)Wt)[lane];
    float4 we = ((const float4*)We)[lane];
    float st = v.x * wt.x + v.y * wt.y + v.z * wt.z + v.w * wt.w;
    float ev = v.x * we.x + v.y * we.y + v.z * we.z + v.w * we.w;
#pragma unroll
    for (int off = 16; off > 0; off >>= 1) {
        st += __shfl_xor_sync(0xFFFFFFFF, st, off);
        ev += __shfl_xor_sync(0xFFFFFFFF, ev, off);
    }
    if (lane == 0) {
        out[i]      = st + bt[0];
        out[NN + i] = ev + be[0];
    }
}

// ---------------- wrappers that bind the __device__ scratch directly ----------
__global__ void k_dummy() {}

// ---------------- launch ----------------
extern "C" void kernel_launch(void* const* d_in, const int* in_sizes, int n_in,
                              void* d_out, int out_size) {
    const float* x  = (const float*)d_in[0];
    const int*   ei = (const int*)  d_in[1];
    const float* W1 = (const float*)d_in[2];
    const float* b1 = (const float*)d_in[3];
    const float* W2 = (const float*)d_in[4];
    const float* b2 = (const float*)d_in[5];
    const float* Wt = (const float*)d_in[6];
    const float* bt = (const float*)d_in[7];
    const float* We = (const float*)d_in[8];
    const float* be = (const float*)d_in[9];
    float* out = (float*)d_out;

    const int* src = ei;        // edge_index[0]
    const int* dst = ei + EE;   // edge_index[1]

    // NOTE: no runtime API calls besides kernel launches — graph-capture safe.
    // Device scratch addresses are taken via unified addressing: &g_bufA[0] is
    // valid on host only through a kernel, so instead we launch kernels that
    // reference the globals directly. To keep the generic k_gemm signature, we
    // obtain the addresses at compile time via small forwarding kernels below.

    const int T = 256;
    int gridN   = (NN + T - 1) / T;
    int gridE   = (EE + T - 1) / T;
    int gridN32 = (NN * 32 + T - 1) / T;
    int gridE32 = (EE * 32 + T - 1) / T;
    int gridG   = (NN + 63) / 64;

    // normalization
    k_init_deg <<<gridN, T>>>();
    k_count_deg<<<gridE, T>>>(dst);
    k_dinv     <<<gridN, T>>>();

    // layer 1
    k_gemm     <<<gridG, T>>>(x, W1, g_bufA, NN);
    k_selfinit <<<gridN32, T>>>(g_bufA, g_agg);
    k_scatter  <<<gridE32, T>>>(g_bufA, src, dst, g_agg);
    k_bias_relu<<<gridN32, T>>>(g_agg, b1, g_bufB);

    // layer 2
    k_gemm     <<<gridG, T>>>(g_bufB, W2, g_bufA, NN);
    k_selfinit <<<gridN32, T>>>(g_bufA, g_agg);
    k_scatter  <<<gridE32, T>>>(g_bufA, src, dst, g_agg);

    // heads
    k_heads    <<<gridN32, T>>>(g_agg, b2, Wt, bt, We, be, out);
}

// round 3
// speedup vs baseline: 2.0320x; 2.0320x over previous
#include <cuda_runtime.h>
#include <cuda_bf16.h>

#define NN 50000
#define EE 800000
#define DD 128
#define NBLK 196          // ceil(50000/256)

// ---------------- scratch (no allocations allowed) ----------------
__device__ int   g_dege[NN];        // edge-only in-degree
__device__ float g_dinv[NN];        // rsqrt(deg_e + 1)
__device__ int   g_rows[NN];        // CSR row start (exclusive scan of dege)
__device__ int   g_cursor[NN];      // fill cursors
__device__ int   g_part[256];       // block partial sums
__device__ int   g_partx[256];      // exclusive scan of partials
__device__ int   g_csrc[EE];        // CSR: source node per slot
__device__ float g_cnrm[EE];        // CSR: edge norm per slot
__device__ float g_bufA[NN * DD];   // gemm output (aggregation input)
__device__ float g_bufB[NN * DD];   // layer-1 activations (gemm2 input)

// ================= CSR build =================
__global__ void k_zero() {
    int i = blockIdx.x * blockDim.x + threadIdx.x;
    if (i < NN) g_dege[i] = 0;
}

__global__ void k_count(const int* __restrict__ dst) {
    int e = blockIdx.x * blockDim.x + threadIdx.x;
    if (e < EE) atomicAdd(&g_dege[dst[e]], 1);
}

// block-level exclusive scan + partial sums
__global__ void k_scanA() {
    __shared__ int s[256];
    int tid = threadIdx.x;
    int i = blockIdx.x * 256 + tid;
    int v = (i < NN) ? g_dege[i] : 0;
    s[tid] = v;
    __syncthreads();
#pragma unroll
    for (int off = 1; off < 256; off <<= 1) {
        int t = (tid >= off) ? s[tid - off] : 0;
        __syncthreads();
        s[tid] += t;
        __syncthreads();
    }
    if (i < NN) g_rows[i] = s[tid] - v;   // local exclusive
    if (tid == 255) g_part[blockIdx.x] = s[255];
}

__global__ void k_scanB() {
    __shared__ int s[256];
    int tid = threadIdx.x;
    int v = (tid < NBLK) ? g_part[tid] : 0;
    s[tid] = v;
    __syncthreads();
#pragma unroll
    for (int off = 1; off < 256; off <<= 1) {
        int t = (tid >= off) ? s[tid - off] : 0;
        __syncthreads();
        s[tid] += t;
        __syncthreads();
    }
    g_partx[tid] = s[tid] - v;            // exclusive
}

__global__ void k_scanC() {
    int i = blockIdx.x * blockDim.x + threadIdx.x;
    if (i >= NN) return;
    int rs = g_rows[i] + g_partx[i >> 8];
    g_rows[i]   = rs;
    g_cursor[i] = rs;
    g_dinv[i]   = rsqrtf((float)(g_dege[i] + 1));
}

__global__ void k_fill(const int* __restrict__ src, const int* __restrict__ dst) {
    int e = blockIdx.x * blockDim.x + threadIdx.x;
    if (e >= EE) return;
    int s = src[e];
    int d = dst[e];
    int pos = atomicAdd(&g_cursor[d], 1);
    g_csrc[pos] = s;
    g_cnrm[pos] = g_dinv[s] * g_dinv[d];
}

// ================= GEMM: Y[M,128] = X[M,128] @ W[128,128] =================
// 256 threads, 64-row x 128-col tile, 8x4 micro-tile.
// sX stored k-major so the inner loop is 3x LDS.128 (2 broadcast) + 32 FFMA.
__global__ void k_gemm(const float* __restrict__ X, const float* __restrict__ W,
                       float* __restrict__ Y, int M) {
    __shared__ float sW[64 * 128];   // 32KB  [k][c]
    __shared__ float sX[64 * 64];    // 16KB  [k][r]

    int tid  = threadIdx.x;
    int row0 = blockIdx.x * 64;
    int nrows = M - row0; if (nrows > 64) nrows = 64;

    int tc = tid & 31;   // cols tc*4 .. tc*4+3
    int tr = tid >> 5;   // rows tr*8 .. tr*8+7  (uniform within warp)

    float acc[8][4];
#pragma unroll
    for (int r = 0; r < 8; r++)
#pragma unroll
        for (int j = 0; j < 4; j++) acc[r][j] = 0.f;

    const float4* W4 = (const float4*)W;
    const float4* X4 = (const float4*)X;

    for (int kk = 0; kk < 128; kk += 64) {
        // W[kk..kk+64][0..128)
        for (int i = tid; i < 64 * 32; i += 256) {
            int k  = i >> 5;
            int c4 = i & 31;
            ((float4*)sW)[i] = W4[(kk + k) * 32 + c4];
        }
        // X tile, transposed into k-major: sX[k][r]
        for (int i = tid; i < 64 * 16; i += 256) {
            int c4 = i >> 6;          // k-group (0..15)
            int r  = i & 63;          // row (consecutive within warp -> conflict-free STS)
            float4 v = make_float4(0.f, 0.f, 0.f, 0.f);
            if (r < nrows) v = X4[(size_t)(row0 + r) * 32 + (kk >> 2) + c4];
            int kb = c4 * 4;
            sX[(kb + 0) * 64 + r] = v.x;
            sX[(kb + 1) * 64 + r] = v.y;
            sX[(kb + 2) * 64 + r] = v.z;
            sX[(kb + 3) * 64 + r] = v.w;
        }
        __syncthreads();

        const float4* sW4 = (const float4*)sW;
        const float4* sX4 = (const float4*)sX;
#pragma unroll
        for (int k = 0; k < 64; k++) {
            float4 w  = sW4[k * 32 + tc];
            float4 xa = sX4[k * 16 + tr * 2];       // rows tr*8..+3 (broadcast)
            float4 xb = sX4[k * 16 + tr * 2 + 1];   // rows tr*8+4..+7 (broadcast)
            acc[0][0] += xa.x * w.x; acc[0][1] += xa.x * w.y; acc[0][2] += xa.x * w.z; acc[0][3] += xa.x * w.w;
            acc[1][0] += xa.y * w.x; acc[1][1] += xa.y * w.y; acc[1][2] += xa.y * w.z; acc[1][3] += xa.y * w.w;
            acc[2][0] += xa.z * w.x; acc[2][1] += xa.z * w.y; acc[2][2] += xa.z * w.z; acc[2][3] += xa.z * w.w;
            acc[3][0] += xa.w * w.x; acc[3][1] += xa.w * w.y; acc[3][2] += xa.w * w.z; acc[3][3] += xa.w * w.w;
            acc[4][0] += xb.x * w.x; acc[4][1] += xb.x * w.y; acc[4][2] += xb.x * w.z; acc[4][3] += xb.x * w.w;
            acc[5][0] += xb.y * w.x; acc[5][1] += xb.y * w.y; acc[5][2] += xb.y * w.z; acc[5][3] += xb.y * w.w;
            acc[6][0] += xb.z * w.x; acc[6][1] += xb.z * w.y; acc[6][2] += xb.z * w.z; acc[6][3] += xb.z * w.w;
            acc[7][0] += xb.w * w.x; acc[7][1] += xb.w * w.y; acc[7][2] += xb.w * w.z; acc[7][3] += xb.w * w.w;
        }
        __syncthreads();
    }

#pragma unroll
    for (int r = 0; r < 8; r++) {
        int row = row0 + tr * 8 + r;
        if (row < M) {
            float4 v = make_float4(acc[r][0], acc[r][1], acc[r][2], acc[r][3]);
            ((float4*)(Y + (size_t)row * DD))[tc] = v;
        }
    }
}

// ================= aggregation: one warp per node, no atomics =================
// acc = H[i]*dinv[i]^2 + sum_{edges->i} H[src]*norm ; epilogue = relu(acc+b) -> out
__global__ void k_agg_relu(const float* __restrict__ H, const float* __restrict__ b,
                           float* __restrict__ out) {
    int gid  = blockIdx.x * blockDim.x + threadIdx.x;
    int i    = gid >> 5;
    if (i >= NN) return;
    int lane = gid & 31;

    const float4* H4 = (const float4*)H;
    float di = g_dinv[i];
    float w  = di * di;
    float4 acc = H4[(size_t)i * 32 + lane];
    acc.x *= w; acc.y *= w; acc.z *= w; acc.w *= w;

    int st = g_rows[i];
    int en = st + g_dege[i];
    for (int j0 = st; j0 < en; j0 += 32) {
        int idx = j0 + lane;
        int   sl = (idx < en) ? g_csrc[idx] : 0;
        float nl = (idx < en) ? g_cnrm[idx] : 0.f;
        int cnt = en - j0; if (cnt > 32) cnt = 32;
        for (int t = 0; t < cnt; t++) {
            int   s  = __shfl_sync(0xFFFFFFFF, sl, t);
            float nm = __shfl_sync(0xFFFFFFFF, nl, t);
            float4 v = H4[(size_t)s * 32 + lane];
            acc.x += v.x * nm; acc.y += v.y * nm; acc.z += v.z * nm; acc.w += v.w * nm;
        }
    }

    float4 bb = ((const float4*)b)[lane];
    acc.x = fmaxf(acc.x + bb.x, 0.f);
    acc.y = fmaxf(acc.y + bb.y, 0.f);
    acc.z = fmaxf(acc.z + bb.z, 0.f);
    acc.w = fmaxf(acc.w + bb.w, 0.f);
    ((float4*)(out + (size_t)i * DD))[lane] = acc;
}

// same aggregation, epilogue = relu(acc+b2) then the two head dot products
__global__ void k_agg_heads(const float* __restrict__ H, const float* __restrict__ b2,
                            const float* __restrict__ Wt, const float* __restrict__ bt,
                            const float* __restrict__ We, const float* __restrict__ be,
                            float* __restrict__ out) {
    int gid  = blockIdx.x * blockDim.x + threadIdx.x;
    int i    = gid >> 5;
    if (i >= NN) return;
    int lane = gid & 31;

    const float4* H4 = (const float4*)H;
    float di = g_dinv[i];
    float w  = di * di;
    float4 acc = H4[(size_t)i * 32 + lane];
    acc.x *= w; acc.y *= w; acc.z *= w; acc.w *= w;

    int st = g_rows[i];
    int en = st + g_dege[i];
    for (int j0 = st; j0 < en; j0 += 32) {
        int idx = j0 + lane;
        int   sl = (idx < en) ? g_csrc[idx] : 0;
        float nl = (idx < en) ? g_cnrm[idx] : 0.f;
        int cnt = en - j0; if (cnt > 32) cnt = 32;
        for (int t = 0; t < cnt; t++) {
            int   s  = __shfl_sync(0xFFFFFFFF, sl, t);
            float nm = __shfl_sync(0xFFFFFFFF, nl, t);
            float4 v = H4[(size_t)s * 32 + lane];
            acc.x += v.x * nm; acc.y += v.y * nm; acc.z += v.z * nm; acc.w += v.w * nm;
        }
    }

    float4 bb = ((const float4*)b2)[lane];
    acc.x = fmaxf(acc.x + bb.x, 0.f);
    acc.y = fmaxf(acc.y + bb.y, 0.f);
    acc.z = fmaxf(acc.z + bb.z, 0.f);
    acc.w = fmaxf(acc.w + bb.w, 0.f);

    float4 wt = ((const float4*)Wt)[lane];
    float4 we = ((const float4*)We)[lane];
    float stv = acc.x * wt.x + acc.y * wt.y + acc.z * wt.z + acc.w * wt.w;
    float evv = acc.x * we.x + acc.y * we.y + acc.z * we.z + acc.w * we.w;
#pragma unroll
    for (int off = 16; off > 0; off >>= 1) {
        stv += __shfl_xor_sync(0xFFFFFFFF, stv, off);
        evv += __shfl_xor_sync(0xFFFFFFFF, evv, off);
    }
    if (lane == 0) {
        out[i]      = stv + bt[0];
        out[NN + i] = evv + be[0];
    }
}

// ================= launch =================
extern "C" void kernel_launch(void* const* d_in, const int* in_sizes, int n_in,
                              void* d_out, int out_size) {
    const float* x  = (const float*)d_in[0];
    const int*   ei = (const int*)  d_in[1];
    const float* W1 = (const float*)d_in[2];
    const float* b1 = (const float*)d_in[3];
    const float* W2 = (const float*)d_in[4];
    const float* b2 = (const float*)d_in[5];
    const float* Wt = (const float*)d_in[6];
    const float* bt = (const float*)d_in[7];
    const float* We = (const float*)d_in[8];
    const float* be = (const float*)d_in[9];
    float* out = (float*)d_out;

    const int* src = ei;        // edge_index[0]
    const int* dst = ei + EE;   // edge_index[1]

    const int T = 256;
    int gridN   = (NN + T - 1) / T;      // 196
    int gridE   = (EE + T - 1) / T;      // 3125
    int gridN32 = (NN * 32 + T - 1) / T; // 6250
    int gridG   = (NN + 63) / 64;        // 782

    // CSR build + normalization
    k_zero  <<<gridN, T>>>();
    k_count <<<gridE, T>>>(dst);
    k_scanA <<<NBLK, 256>>>();
    k_scanB <<<1, 256>>>();
    k_scanC <<<gridN, T>>>();
    k_fill  <<<gridE, T>>>(src, dst);

    // layer 1
    k_gemm     <<<gridG, T>>>(x, W1, g_bufA, NN);
    k_agg_relu <<<gridN32, T>>>(g_bufA, b1, g_bufB);

    // layer 2
    k_gemm     <<<gridG, T>>>(g_bufB, W2, g_bufA, NN);
    k_agg_heads<<<gridN32, T>>>(g_bufA, b2, Wt, bt, We, be, out);
}

// round 6
// speedup vs baseline: 38.7650x; 19.0772x over previous
#include <cuda_runtime.h>
#include <cuda_bf16.h>

#define NN 50000
#define EE 800000
#define DD 128
#define NBLK 196          // ceil(50000/256)

// ---------------- scratch (no allocations allowed) ----------------
// NEVER passed from host as kernel args (host-side symbol = ATS host memory!).
// Every kernel touching these references them directly in device code.
__device__ int   g_dege[NN];        // edge-only in-degree
__device__ float g_dinv[NN];        // rsqrt(deg_e + 1)
__device__ int   g_rows[NN];        // CSR row start (exclusive scan of dege)
__device__ int   g_cursor[NN];      // fill cursors
__device__ int   g_part[256];       // block partial sums
__device__ int   g_partx[256];      // exclusive scan of partials
__device__ int   g_csrc[EE];        // CSR: source node per slot
__device__ float g_cnrm[EE];        // CSR: edge norm per slot
__device__ float g_bufA[NN * DD];   // gemm output (aggregation input)
__device__ float g_bufB[NN * DD];   // layer-1 activations (gemm2 input)

// ================= CSR build =================
__global__ void k_zero() {
    int i = blockIdx.x * blockDim.x + threadIdx.x;
    if (i < NN) g_dege[i] = 0;
}

__global__ void k_count(const int* __restrict__ dst) {
    int e = blockIdx.x * blockDim.x + threadIdx.x;
    if (e < EE) atomicAdd(&g_dege[dst[e]], 1);
}

__global__ void k_scanA() {
    __shared__ int s[256];
    int tid = threadIdx.x;
    int i = blockIdx.x * 256 + tid;
    int v = (i < NN) ? g_dege[i] : 0;
    s[tid] = v;
    __syncthreads();
#pragma unroll
    for (int off = 1; off < 256; off <<= 1) {
        int t = (tid >= off) ? s[tid - off] : 0;
        __syncthreads();
        s[tid] += t;
        __syncthreads();
    }
    if (i < NN) g_rows[i] = s[tid] - v;   // local exclusive
    if (tid == 255) g_part[blockIdx.x] = s[255];
}

__global__ void k_scanB() {
    __shared__ int s[256];
    int tid = threadIdx.x;
    int v = (tid < NBLK) ? g_part[tid] : 0;
    s[tid] = v;
    __syncthreads();
#pragma unroll
    for (int off = 1; off < 256; off <<= 1) {
        int t = (tid >= off) ? s[tid - off] : 0;
        __syncthreads();
        s[tid] += t;
        __syncthreads();
    }
    g_partx[tid] = s[tid] - v;            // exclusive
}

__global__ void k_scanC() {
    int i = blockIdx.x * blockDim.x + threadIdx.x;
    if (i >= NN) return;
    int rs = g_rows[i] + g_partx[i >> 8];
    g_rows[i]   = rs;
    g_cursor[i] = rs;
    g_dinv[i]   = rsqrtf((float)(g_dege[i] + 1));
}

__global__ void k_fill(const int* __restrict__ src, const int* __restrict__ dst) {
    int e = blockIdx.x * blockDim.x + threadIdx.x;
    if (e >= EE) return;
    int s = src[e];
    int d = dst[e];
    int pos = atomicAdd(&g_cursor[d], 1);
    g_csrc[pos] = s;
    g_cnrm[pos] = g_dinv[s] * g_dinv[d];
}

// ================= GEMM core: Y[M,128] = X[M,128] @ W[128,128] =================
// 256 threads, 64-row x 128-col tile, 8x4 micro-tile; sX stored k-major so the
// inner loop is 3x LDS.128 (2 warp-uniform broadcasts) + 32 FFMA per k.
__device__ __forceinline__ void gemm_core(const float* __restrict__ X,
                                          const float* __restrict__ W,
                                          float* __restrict__ Y, int M) {
    __shared__ float sW[64 * 128];   // 32KB  [k][c]
    __shared__ float sX[64 * 64];    // 16KB  [k][r]

    int tid  = threadIdx.x;
    int row0 = blockIdx.x * 64;
    int nrows = M - row0; if (nrows > 64) nrows = 64;

    int tc = tid & 31;
    int tr = tid >> 5;

    float acc[8][4];
#pragma unroll
    for (int r = 0; r < 8; r++)
#pragma unroll
        for (int j = 0; j < 4; j++) acc[r][j] = 0.f;

    const float4* W4 = (const float4*)W;
    const float4* X4 = (const float4*)X;

    for (int kk = 0; kk < 128; kk += 64) {
        for (int i = tid; i < 64 * 32; i += 256) {
            int k  = i >> 5;
            int c4 = i & 31;
            ((float4*)sW)[i] = W4[(kk + k) * 32 + c4];
        }
        for (int i = tid; i < 64 * 16; i += 256) {
            int c4 = i >> 6;
            int r  = i & 63;
            float4 v = make_float4(0.f, 0.f, 0.f, 0.f);
            if (r < nrows) v = X4[(size_t)(row0 + r) * 32 + (kk >> 2) + c4];
            int kb = c4 * 4;
            sX[(kb + 0) * 64 + r] = v.x;
            sX[(kb + 1) * 64 + r] = v.y;
            sX[(kb + 2) * 64 + r] = v.z;
            sX[(kb + 3) * 64 + r] = v.w;
        }
        __syncthreads();

        const float4* sW4 = (const float4*)sW;
        const float4* sX4 = (const float4*)sX;
#pragma unroll
        for (int k = 0; k < 64; k++) {
            float4 w  = sW4[k * 32 + tc];
            float4 xa = sX4[k * 16 + tr * 2];
            float4 xb = sX4[k * 16 + tr * 2 + 1];
            acc[0][0] += xa.x * w.x; acc[0][1] += xa.x * w.y; acc[0][2] += xa.x * w.z; acc[0][3] += xa.x * w.w;
            acc[1][0] += xa.y * w.x; acc[1][1] += xa.y * w.y; acc[1][2] += xa.y * w.z; acc[1][3] += xa.y * w.w;
            acc[2][0] += xa.z * w.x; acc[2][1] += xa.z * w.y; acc[2][2] += xa.z * w.z; acc[2][3] += xa.z * w.w;
            acc[3][0] += xa.w * w.x; acc[3][1] += xa.w * w.y; acc[3][2] += xa.w * w.z; acc[3][3] += xa.w * w.w;
            acc[4][0] += xb.x * w.x; acc[4][1] += xb.x * w.y; acc[4][2] += xb.x * w.z; acc[4][3] += xb.x * w.w;
            acc[5][0] += xb.y * w.x; acc[5][1] += xb.y * w.y; acc[5][2] += xb.y * w.z; acc[5][3] += xb.y * w.w;
            acc[6][0] += xb.z * w.x; acc[6][1] += xb.z * w.y; acc[6][2] += xb.z * w.z; acc[6][3] += xb.z * w.w;
            acc[7][0] += xb.w * w.x; acc[7][1] += xb.w * w.y; acc[7][2] += xb.w * w.z; acc[7][3] += xb.w * w.w;
        }
        __syncthreads();
    }

#pragma unroll
    for (int r = 0; r < 8; r++) {
        int row = row0 + tr * 8 + r;
        if (row < M) {
            float4 v = make_float4(acc[r][0], acc[r][1], acc[r][2], acc[r][3]);
            ((float4*)(Y + (size_t)row * DD))[tc] = v;
        }
    }
}

// wrappers bind the device-global buffers IN DEVICE CODE (true device addresses)
__global__ void __launch_bounds__(256) k_gemm1(const float* __restrict__ X,
                                               const float* __restrict__ W) {
    gemm_core(X, W, g_bufA, NN);
}
__global__ void __launch_bounds__(256) k_gemm2(const float* __restrict__ W) {
    gemm_core(g_bufB, W, g_bufA, NN);
}

// ================= aggregation: warp per node, ILP-4 gathers, no atomics ======
__device__ __forceinline__ float4 agg_node(int i, int lane) {
    const float4* H4 = (const float4*)g_bufA;
    float di = g_dinv[i];
    float w  = di * di;
    float4 acc = H4[(size_t)i * 32 + lane];
    acc.x *= w; acc.y *= w; acc.z *= w; acc.w *= w;

    int j  = g_rows[i];
    int en = j + g_dege[i];
    for (; j + 4 <= en; j += 4) {
        int   s0 = __ldg(&g_csrc[j]);
        int   s1 = __ldg(&g_csrc[j + 1]);
        int   s2 = __ldg(&g_csrc[j + 2]);
        int   s3 = __ldg(&g_csrc[j + 3]);
        float n0 = __ldg(&g_cnrm[j]);
        float n1 = __ldg(&g_cnrm[j + 1]);
        float n2 = __ldg(&g_cnrm[j + 2]);
        float n3 = __ldg(&g_cnrm[j + 3]);
        float4 v0 = H4[(size_t)s0 * 32 + lane];
        float4 v1 = H4[(size_t)s1 * 32 + lane];
        float4 v2 = H4[(size_t)s2 * 32 + lane];
        float4 v3 = H4[(size_t)s3 * 32 + lane];
        acc.x += v0.x * n0; acc.y += v0.y * n0; acc.z += v0.z * n0; acc.w += v0.w * n0;
        acc.x += v1.x * n1; acc.y += v1.y * n1; acc.z += v1.z * n1; acc.w += v1.w * n1;
        acc.x += v2.x * n2; acc.y += v2.y * n2; acc.z += v2.z * n2; acc.w += v2.w * n2;
        acc.x += v3.x * n3; acc.y += v3.y * n3; acc.z += v3.z * n3; acc.w += v3.w * n3;
    }
    for (; j < en; j++) {
        int   s = __ldg(&g_csrc[j]);
        float n = __ldg(&g_cnrm[j]);
        float4 v = H4[(size_t)s * 32 + lane];
        acc.x += v.x * n; acc.y += v.y * n; acc.z += v.z * n; acc.w += v.w * n;
    }
    return acc;
}

// layer-1 epilogue: relu(acc + b1) -> g_bufB
__global__ void k_agg_relu(const float* __restrict__ b) {
    int gid  = blockIdx.x * blockDim.x + threadIdx.x;
    int i    = gid >> 5;
    if (i >= NN) return;
    int lane = gid & 31;

    float4 acc = agg_node(i, lane);
    float4 bb = ((const float4*)b)[lane];
    acc.x = fmaxf(acc.x + bb.x, 0.f);
    acc.y = fmaxf(acc.y + bb.y, 0.f);
    acc.z = fmaxf(acc.z + bb.z, 0.f);
    acc.w = fmaxf(acc.w + bb.w, 0.f);
    ((float4*)(g_bufB + (size_t)i * DD))[lane] = acc;
}

// layer-2 epilogue: relu(acc + b2), then two head dot-products -> out
__global__ void k_agg_heads(const float* __restrict__ b2,
                            const float* __restrict__ Wt, const float* __restrict__ bt,
                            const float* __restrict__ We, const float* __restrict__ be,
                            float* __restrict__ out) {
    int gid  = blockIdx.x * blockDim.x + threadIdx.x;
    int i    = gid >> 5;
    if (i >= NN) return;
    int lane = gid & 31;

    float4 acc = agg_node(i, lane);
    float4 bb = ((const float4*)b2)[lane];
    acc.x = fmaxf(acc.x + bb.x, 0.f);
    acc.y = fmaxf(acc.y + bb.y, 0.f);
    acc.z = fmaxf(acc.z + bb.z, 0.f);
    acc.w = fmaxf(acc.w + bb.w, 0.f);

    float4 wt = ((const float4*)Wt)[lane];
    float4 we = ((const float4*)We)[lane];
    float stv = acc.x * wt.x + acc.y * wt.y + acc.z * wt.z + acc.w * wt.w;
    float evv = acc.x * we.x + acc.y * we.y + acc.z * we.z + acc.w * we.w;
#pragma unroll
    for (int off = 16; off > 0; off >>= 1) {
        stv += __shfl_xor_sync(0xFFFFFFFF, stv, off);
        evv += __shfl_xor_sync(0xFFFFFFFF, evv, off);
    }
    if (lane == 0) {
        out[i]      = stv + bt[0];
        out[NN + i] = evv + be[0];
    }
}

// ================= launch =================
extern "C" void kernel_launch(void* const* d_in, const int* in_sizes, int n_in,
                              void* d_out, int out_size) {
    const float* x  = (const float*)d_in[0];
    const int*   ei = (const int*)  d_in[1];
    const float* W1 = (const float*)d_in[2];
    const float* b1 = (const float*)d_in[3];
    const float* W2 = (const float*)d_in[4];
    const float* b2 = (const float*)d_in[5];
    const float* Wt = (const float*)d_in[6];
    const float* bt = (const float*)d_in[7];
    const float* We = (const float*)d_in[8];
    const float* be = (const float*)d_in[9];
    float* out = (float*)d_out;

    const int* src = ei;        // edge_index[0]
    const int* dst = ei + EE;   // edge_index[1]

    const int T = 256;
    int gridN   = (NN + T - 1) / T;      // 196
    int gridE   = (EE + T - 1) / T;      // 3125
    int gridN32 = (NN * 32 + T - 1) / T; // 6250
    int gridG   = (NN + 63) / 64;        // 782

    // CSR build + normalization
    k_zero  <<<gridN, T>>>();
    k_count <<<gridE, T>>>(dst);
    k_scanA <<<NBLK, 256>>>();
    k_scanB <<<1, 256>>>();
    k_scanC <<<gridN, T>>>();
    k_fill  <<<gridE, T>>>(src, dst);

    // layer 1
    k_gemm1    <<<gridG, T>>>(x, W1);
    k_agg_relu <<<gridN32, T>>>(b1);

    // layer 2
    k_gemm2    <<<gridG, T>>>(W2);
    k_agg_heads<<<gridN32, T>>>(b2, Wt, bt, We, be, out);
}

// round 7
// speedup vs baseline: 58.8139x; 1.5172x over previous
#include <cuda_runtime.h>
#include <cuda_bf16.h>

#define NN 50000
#define EE 800000
#define DD 128
#define NBLK 196          // ceil(50000/256)

typedef unsigned long long u64;

// ---------------- scratch (no allocations allowed) ----------------
// NEVER passed from host as kernel args (host-side symbol = ATS host memory!).
// Every kernel touching these references them directly in device code.
__device__ int   g_dege[NN];        // edge-only in-degree
__device__ float g_dinv[NN];        // rsqrt(deg_e + 1)
__device__ int   g_rows[NN];        // CSR row start (exclusive scan of dege)
__device__ int   g_cursor[NN];      // fill cursors
__device__ int   g_part[256];       // block partial sums
__device__ int   g_partx[256];      // exclusive scan of partials
__device__ int   g_csrc[EE];        // CSR: source node per slot
__device__ float g_bufA[NN * DD];   // gemm output (aggregation input)
__device__ float g_bufB[NN * DD];   // layer-1 activations (gemm2 input)

// ================= CSR build =================
__global__ void k_zero() {
    int i = blockIdx.x * blockDim.x + threadIdx.x;
    if (i < NN) g_dege[i] = 0;
}

__global__ void k_count(const int* __restrict__ dst) {
    int e = blockIdx.x * blockDim.x + threadIdx.x;
    if (e < EE) atomicAdd(&g_dege[dst[e]], 1);
}

__global__ void k_scanA() {
    __shared__ int s[256];
    int tid = threadIdx.x;
    int i = blockIdx.x * 256 + tid;
    int v = (i < NN) ? g_dege[i] : 0;
    s[tid] = v;
    __syncthreads();
#pragma unroll
    for (int off = 1; off < 256; off <<= 1) {
        int t = (tid >= off) ? s[tid - off] : 0;
        __syncthreads();
        s[tid] += t;
        __syncthreads();
    }
    if (i < NN) g_rows[i] = s[tid] - v;   // local exclusive
    if (tid == 255) g_part[blockIdx.x] = s[255];
}

__global__ void k_scanB() {
    __shared__ int s[256];
    int tid = threadIdx.x;
    int v = (tid < NBLK) ? g_part[tid] : 0;
    s[tid] = v;
    __syncthreads();
#pragma unroll
    for (int off = 1; off < 256; off <<= 1) {
        int t = (tid >= off) ? s[tid - off] : 0;
        __syncthreads();
        s[tid] += t;
        __syncthreads();
    }
    g_partx[tid] = s[tid] - v;            // exclusive
}

__global__ void k_scanC() {
    int i = blockIdx.x * blockDim.x + threadIdx.x;
    if (i >= NN) return;
    int rs = g_rows[i] + g_partx[i >> 8];
    g_rows[i]   = rs;
    g_cursor[i] = rs;
    g_dinv[i]   = rsqrtf((float)(g_dege[i] + 1));
}

__global__ void k_fill(const int* __restrict__ src, const int* __restrict__ dst) {
    int e = blockIdx.x * blockDim.x + threadIdx.x;
    if (e >= EE) return;
    int d = dst[e];
    int pos = atomicAdd(&g_cursor[d], 1);
    g_csrc[pos] = src[e];
}

// ================= GEMM core: Y[M,128] = X[M,128] @ W[128,128] =================
// 256 threads, 64-row x 128-col tile, 8 rows x 4 cols per thread held as
// 4 row-pair f32x2 accumulators x 4 cols. Inner loop per k:
//   1x LDS.128 (w, conflict-free) + 4x LDS.64 (x row-pairs, warp-uniform)
//   + 4x mov.b64 dup (ALU pipe) + 16x fma.rn.f32x2 (FFMA2 = 2x fp32 rate).
__device__ __forceinline__ void gemm_core(const float* __restrict__ X,
                                          const float* __restrict__ W,
                                          float* __restrict__ Y, int M) {
    __shared__ float sW[64 * 128];   // 32KB  [k][c]
    __shared__ float sX[64 * 64];    // 16KB  [k][r]

    int tid  = threadIdx.x;
    int row0 = blockIdx.x * 64;
    int nrows = M - row0; if (nrows > 64) nrows = 64;

    int tc = tid & 31;   // cols tc*4 .. tc*4+3
    int tr = tid >> 5;   // rows tr*8 .. tr*8+7 (uniform within warp)

    u64 acc2[4][4];      // [row-pair][col], f32x2 = (row 2rp, row 2rp+1)
#pragma unroll
    for (int rp = 0; rp < 4; rp++)
#pragma unroll
        for (int c = 0; c < 4; c++) acc2[rp][c] = 0ULL;

    const float4* W4 = (const float4*)W;
    const float4* X4 = (const float4*)X;

    for (int kk = 0; kk < 128; kk += 64) {
        for (int i = tid; i < 64 * 32; i += 256) {
            int k  = i >> 5;
            int c4 = i & 31;
            ((float4*)sW)[i] = W4[(kk + k) * 32 + c4];
        }
        for (int i = tid; i < 64 * 16; i += 256) {
            int c4 = i >> 6;
            int r  = i & 63;
            float4 v = make_float4(0.f, 0.f, 0.f, 0.f);
            if (r < nrows) v = X4[(size_t)(row0 + r) * 32 + (kk >> 2) + c4];
            int kb = c4 * 4;
            sX[(kb + 0) * 64 + r] = v.x;
            sX[(kb + 1) * 64 + r] = v.y;
            sX[(kb + 2) * 64 + r] = v.z;
            sX[(kb + 3) * 64 + r] = v.w;
        }
        __syncthreads();

        const float4* sW4 = (const float4*)sW;
        const u64*    sX2 = (const u64*)sX;
#pragma unroll
        for (int k = 0; k < 64; k++) {
            float4 w = sW4[k * 32 + tc];
            u64 wd[4];
            asm("mov.b64 %0, {%1, %1};" : "=l"(wd[0]) : "r"(__float_as_uint(w.x)));
            asm("mov.b64 %0, {%1, %1};" : "=l"(wd[1]) : "r"(__float_as_uint(w.y)));
            asm("mov.b64 %0, {%1, %1};" : "=l"(wd[2]) : "r"(__float_as_uint(w.z)));
            asm("mov.b64 %0, {%1, %1};" : "=l"(wd[3]) : "r"(__float_as_uint(w.w)));
            u64 xp[4];
            xp[0] = sX2[k * 32 + tr * 4 + 0];   // rows 8tr+0,1 (uniform broadcast)
            xp[1] = sX2[k * 32 + tr * 4 + 1];   // rows 8tr+2,3
            xp[2] = sX2[k * 32 + tr * 4 + 2];   // rows 8tr+4,5
            xp[3] = sX2[k * 32 + tr * 4 + 3];   // rows 8tr+6,7
#pragma unroll
            for (int rp = 0; rp < 4; rp++) {
#pragma unroll
                for (int c = 0; c < 4; c++) {
                    asm("fma.rn.f32x2 %0, %1, %2, %0;"
                        : "+l"(acc2[rp][c]) : "l"(xp[rp]), "l"(wd[c]));
                }
            }
        }
        __syncthreads();
    }

#pragma unroll
    for (int rp = 0; rp < 4; rp++) {
        unsigned lo[4], hi[4];
#pragma unroll
        for (int c = 0; c < 4; c++)
            asm("mov.b64 {%0, %1}, %2;" : "=r"(lo[c]), "=r"(hi[c]) : "l"(acc2[rp][c]));
        int rowe = row0 + tr * 8 + rp * 2;
        if (rowe < M) {
            float4 v = make_float4(__uint_as_float(lo[0]), __uint_as_float(lo[1]),
                                   __uint_as_float(lo[2]), __uint_as_float(lo[3]));
            ((float4*)(Y + (size_t)rowe * DD))[tc] = v;
        }
        if (rowe + 1 < M) {
            float4 v = make_float4(__uint_as_float(hi[0]), __uint_as_float(hi[1]),
                                   __uint_as_float(hi[2]), __uint_as_float(hi[3]));
            ((float4*)(Y + (size_t)(rowe + 1) * DD))[tc] = v;
        }
    }
}

// wrappers bind the device-global buffers IN DEVICE CODE (true device addresses)
__global__ void __launch_bounds__(256) k_gemm1(const float* __restrict__ X,
                                               const float* __restrict__ W) {
    gemm_core(X, W, g_bufA, NN);
}
__global__ void __launch_bounds__(256) k_gemm2(const float* __restrict__ W) {
    gemm_core(g_bufB, W, g_bufA, NN);
}

// ================= aggregation: warp per node, ILP-4 gathers, no atomics ======
// res = dinv[i] * ( sum_{s->i} H[s]*dinv[s]  +  dinv[i]*H[i] )
__device__ __forceinline__ float4 agg_node(int i, int lane) {
    const float4* H4 = (const float4*)g_bufA;
    float di = g_dinv[i];

    float4 accE = make_float4(0.f, 0.f, 0.f, 0.f);
    int j  = g_rows[i];
    int en = j + g_dege[i];
    for (; j + 4 <= en; j += 4) {
        int   s0 = __ldg(&g_csrc[j]);
        int   s1 = __ldg(&g_csrc[j + 1]);
        int   s2 = __ldg(&g_csrc[j + 2]);
        int   s3 = __ldg(&g_csrc[j + 3]);
        float n0 = __ldg(&g_dinv[s0]);
        float n1 = __ldg(&g_dinv[s1]);
        float n2 = __ldg(&g_dinv[s2]);
        float n3 = __ldg(&g_dinv[s3]);
        float4 v0 = H4[(size_t)s0 * 32 + lane];
        float4 v1 = H4[(size_t)s1 * 32 + lane];
        float4 v2 = H4[(size_t)s2 * 32 + lane];
        float4 v3 = H4[(size_t)s3 * 32 + lane];
        accE.x += v0.x * n0; accE.y += v0.y * n0; accE.z += v0.z * n0; accE.w += v0.w * n0;
        accE.x += v1.x * n1; accE.y += v1.y * n1; accE.z += v1.z * n1; accE.w += v1.w * n1;
        accE.x += v2.x * n2; accE.y += v2.y * n2; accE.z += v2.z * n2; accE.w += v2.w * n2;
        accE.x += v3.x * n3; accE.y += v3.y * n3; accE.z += v3.z * n3; accE.w += v3.w * n3;
    }
    for (; j < en; j++) {
        int   s = __ldg(&g_csrc[j]);
        float n = __ldg(&g_dinv[s]);
        float4 v = H4[(size_t)s * 32 + lane];
        accE.x += v.x * n; accE.y += v.y * n; accE.z += v.z * n; accE.w += v.w * n;
    }

    float4 self = H4[(size_t)i * 32 + lane];
    float4 res;
    res.x = di * (accE.x + di * self.x);
    res.y = di * (accE.y + di * self.y);
    res.z = di * (accE.z + di * self.z);
    res.w = di * (accE.w + di * self.w);
    return res;
}

// layer-1 epilogue: relu(acc + b1) -> g_bufB
__global__ void k_agg_relu(const float* __restrict__ b) {
    int gid  = blockIdx.x * blockDim.x + threadIdx.x;
    int i    = gid >> 5;
    if (i >= NN) return;
    int lane = gid & 31;

    float4 acc = agg_node(i, lane);
    float4 bb = ((const float4*)b)[lane];
    acc.x = fmaxf(acc.x + bb.x, 0.f);
    acc.y = fmaxf(acc.y + bb.y, 0.f);
    acc.z = fmaxf(acc.z + bb.z, 0.f);
    acc.w = fmaxf(acc.w + bb.w, 0.f);
    ((float4*)(g_bufB + (size_t)i * DD))[lane] = acc;
}

// layer-2 epilogue: relu(acc + b2), then two head dot-products -> out
__global__ void k_agg_heads(const float* __restrict__ b2,
                            const float* __restrict__ Wt, const float* __restrict__ bt,
                            const float* __restrict__ We, const float* __restrict__ be,
                            float* __restrict__ out) {
    int gid  = blockIdx.x * blockDim.x + threadIdx.x;
    int i    = gid >> 5;
    if (i >= NN) return;
    int lane = gid & 31;

    float4 acc = agg_node(i, lane);
    float4 bb = ((const float4*)b2)[lane];
    acc.x = fmaxf(acc.x + bb.x, 0.f);
    acc.y = fmaxf(acc.y + bb.y, 0.f);
    acc.z = fmaxf(acc.z + bb.z, 0.f);
    acc.w = fmaxf(acc.w + bb.w, 0.f);

    float4 wt = ((const float4*)Wt)[lane];
    float4 we = ((const float4*)We)[lane];
    float stv = acc.x * wt.x + acc.y * wt.y + acc.z * wt.z + acc.w * wt.w;
    float evv = acc.x * we.x + acc.y * we.y + acc.z * we.z + acc.w * we.w;
#pragma unroll
    for (int off = 16; off > 0; off >>= 1) {
        stv += __shfl_xor_sync(0xFFFFFFFF, stv, off);
        evv += __shfl_xor_sync(0xFFFFFFFF, evv, off);
    }
    if (lane == 0) {
        out[i]      = stv + bt[0];
        out[NN + i] = evv + be[0];
    }
}

// ================= launch =================
extern "C" void kernel_launch(void* const* d_in, const int* in_sizes, int n_in,
                              void* d_out, int out_size) {
    const float* x  = (const float*)d_in[0];
    const int*   ei = (const int*)  d_in[1];
    const float* W1 = (const float*)d_in[2];
    const float* b1 = (const float*)d_in[3];
    const float* W2 = (const float*)d_in[4];
    const float* b2 = (const float*)d_in[5];
    const float* Wt = (const float*)d_in[6];
    const float* bt = (const float*)d_in[7];
    const float* We = (const float*)d_in[8];
    const float* be = (const float*)d_in[9];
    float* out = (float*)d_out;

    const int* src = ei;        // edge_index[0]
    const int* dst = ei + EE;   // edge_index[1]

    const int T = 256;
    int gridN   = (NN + T - 1) / T;      // 196
    int gridE   = (EE + T - 1) / T;      // 3125
    int gridN32 = (NN * 32 + T - 1) / T; // 6250
    int gridG   = (NN + 63) / 64;        // 782

    // CSR build + normalization
    k_zero  <<<gridN, T>>>();
    k_count <<<gridE, T>>>(dst);
    k_scanA <<<NBLK, 256>>>();
    k_scanB <<<1, 256>>>();
    k_scanC <<<gridN, T>>>();
    k_fill  <<<gridE, T>>>(src, dst);

    // layer 1
    k_gemm1    <<<gridG, T>>>(x, W1);
    k_agg_relu <<<gridN32, T>>>(b1);

    // layer 2
    k_gemm2    <<<gridG, T>>>(W2);
    k_agg_heads<<<gridN32, T>>>(b2, Wt, bt, We, be, out);
}

// round 8
// speedup vs baseline: 67.2986x; 1.1443x over previous
#include <cuda_runtime.h>
#include <cuda_bf16.h>

#define NN 50000
#define EE 800000
#define DD 128
#define NBLK 196          // ceil(50000/256)
#define GRIDG 782         // ceil(50000/64) gemm tiles
#define GRIDE 3125        // ceil(800000/256)

typedef unsigned long long u64;

// ---------------- scratch (no allocations allowed) ----------------
// NEVER passed from host as kernel args (host-side symbol = ATS host memory!).
// Every kernel touching these references them directly in device code.
__device__ int   g_dege[NN];        // edge-only in-degree
__device__ float g_dinv[NN];        // rsqrt(deg_e + 1)
__device__ int   g_rows[NN];        // CSR row start (exclusive scan of dege)
__device__ int   g_cursor[NN];      // fill cursors
__device__ int   g_part[256];       // block partial sums
__device__ int   g_csrc[EE];        // CSR: source node per slot
__device__ float g_bufA[NN * DD];   // pre-scaled gemm output Hs = (XW)*dinv
__device__ float g_bufB[NN * DD];   // layer-1 activations (gemm2 input)

// ================= CSR build =================
__global__ void k_zero() {
    int i = blockIdx.x * blockDim.x + threadIdx.x;
    if (i < NN) g_dege[i] = 0;
}

__global__ void k_count(const int* __restrict__ dst) {
    int e = blockIdx.x * blockDim.x + threadIdx.x;
    if (e < EE) atomicAdd(&g_dege[dst[e]], 1);
}

__global__ void k_scanA() {
    __shared__ int s[256];
    int tid = threadIdx.x;
    int i = blockIdx.x * 256 + tid;
    int v = (i < NN) ? g_dege[i] : 0;
    s[tid] = v;
    __syncthreads();
#pragma unroll
    for (int off = 1; off < 256; off <<= 1) {
        int t = (tid >= off) ? s[tid - off] : 0;
        __syncthreads();
        s[tid] += t;
        __syncthreads();
    }
    if (i < NN) g_rows[i] = s[tid] - v;   // local exclusive
    if (tid == 255) g_part[blockIdx.x] = s[255];
}

// finalize: each block computes its own prefix of the 196 partials (cheap),
// then applies offset, writes cursors and dinv.  (replaces scanB+scanC)
__global__ void k_scanC() {
    __shared__ int s[256];
    int tid = threadIdx.x;
    s[tid] = (tid < (int)blockIdx.x && tid < NBLK) ? g_part[tid] : 0;
    __syncthreads();
#pragma unroll
    for (int off = 128; off > 0; off >>= 1) {
        if (tid < off) s[tid] += s[tid + off];
        __syncthreads();
    }
    int offset = s[0];
    int i = blockIdx.x * 256 + tid;
    if (i >= NN) return;
    int rs = g_rows[i] + offset;
    g_rows[i]   = rs;
    g_cursor[i] = rs;
    g_dinv[i]   = rsqrtf((float)(g_dege[i] + 1));
}

// ================= GEMM core: Hs[M,128] = (X[M,128] @ W[128,128]) * dinv =====
// 256 threads, 64-row x 128-col tile, 8 rows x 4 cols per thread held as
// 4 row-pair f32x2 accumulators x 4 cols. Inner loop per k:
//   1x LDS.128 (w) + 4x LDS.64 (x row-pairs, warp-uniform) + 4x mov.b64 dup
//   + 16x fma.rn.f32x2 (FFMA2 = 2x fp32 rate).
__device__ __forceinline__ void gemm_core(int bid, const float* __restrict__ X,
                                          const float* __restrict__ W,
                                          float* __restrict__ Y, int M) {
    __shared__ float sW[64 * 128];   // 32KB  [k][c]
    __shared__ float sX[64 * 64];    // 16KB  [k][r]

    int tid  = threadIdx.x;
    int row0 = bid * 64;
    int nrows = M - row0; if (nrows > 64) nrows = 64;

    int tc = tid & 31;   // cols tc*4 .. tc*4+3
    int tr = tid >> 5;   // rows tr*8 .. tr*8+7 (uniform within warp)

    u64 acc2[4][4];      // [row-pair][col], f32x2 = (row 2rp, row 2rp+1)
#pragma unroll
    for (int rp = 0; rp < 4; rp++)
#pragma unroll
        for (int c = 0; c < 4; c++) acc2[rp][c] = 0ULL;

    const float4* W4 = (const float4*)W;
    const float4* X4 = (const float4*)X;

    for (int kk = 0; kk < 128; kk += 64) {
        for (int i = tid; i < 64 * 32; i += 256) {
            int k  = i >> 5;
            int c4 = i & 31;
            ((float4*)sW)[i] = W4[(kk + k) * 32 + c4];
        }
        for (int i = tid; i < 64 * 16; i += 256) {
            int c4 = i >> 6;
            int r  = i & 63;
            float4 v = make_float4(0.f, 0.f, 0.f, 0.f);
            if (r < nrows) v = X4[(size_t)(row0 + r) * 32 + (kk >> 2) + c4];
            int kb = c4 * 4;
            sX[(kb + 0) * 64 + r] = v.x;
            sX[(kb + 1) * 64 + r] = v.y;
            sX[(kb + 2) * 64 + r] = v.z;
            sX[(kb + 3) * 64 + r] = v.w;
        }
        __syncthreads();

        const float4* sW4 = (const float4*)sW;
        const u64*    sX2 = (const u64*)sX;
#pragma unroll
        for (int k = 0; k < 64; k++) {
            float4 w = sW4[k * 32 + tc];
            u64 wd[4];
            asm("mov.b64 %0, {%1, %1};" : "=l"(wd[0]) : "r"(__float_as_uint(w.x)));
            asm("mov.b64 %0, {%1, %1};" : "=l"(wd[1]) : "r"(__float_as_uint(w.y)));
            asm("mov.b64 %0, {%1, %1};" : "=l"(wd[2]) : "r"(__float_as_uint(w.z)));
            asm("mov.b64 %0, {%1, %1};" : "=l"(wd[3]) : "r"(__float_as_uint(w.w)));
            u64 xp[4];
            xp[0] = sX2[k * 32 + tr * 4 + 0];
            xp[1] = sX2[k * 32 + tr * 4 + 1];
            xp[2] = sX2[k * 32 + tr * 4 + 2];
            xp[3] = sX2[k * 32 + tr * 4 + 3];
#pragma unroll
            for (int rp = 0; rp < 4; rp++) {
#pragma unroll
                for (int c = 0; c < 4; c++) {
                    asm("fma.rn.f32x2 %0, %1, %2, %0;"
                        : "+l"(acc2[rp][c]) : "l"(xp[rp]), "l"(wd[c]));
                }
            }
        }
        __syncthreads();
    }

#pragma unroll
    for (int rp = 0; rp < 4; rp++) {
        unsigned lo[4], hi[4];
#pragma unroll
        for (int c = 0; c < 4; c++)
            asm("mov.b64 {%0, %1}, %2;" : "=r"(lo[c]), "=r"(hi[c]) : "l"(acc2[rp][c]));
        int rowe = row0 + tr * 8 + rp * 2;
        if (rowe < M) {
            float d = g_dinv[rowe];
            float4 v = make_float4(__uint_as_float(lo[0]) * d, __uint_as_float(lo[1]) * d,
                                   __uint_as_float(lo[2]) * d, __uint_as_float(lo[3]) * d);
            ((float4*)(Y + (size_t)rowe * DD))[tc] = v;
        }
        if (rowe + 1 < M) {
            float d = g_dinv[rowe + 1];
            float4 v = make_float4(__uint_as_float(hi[0]) * d, __uint_as_float(hi[1]) * d,
                                   __uint_as_float(hi[2]) * d, __uint_as_float(hi[3]) * d);
            ((float4*)(Y + (size_t)(rowe + 1) * DD))[tc] = v;
        }
    }
}

// fused: blocks [0, GRIDG) run gemm1 (x@W1 -> scaled bufA);
//        blocks [GRIDG, GRIDG+GRIDE) run the independent CSR fill.
__global__ void __launch_bounds__(256) k_fill_gemm1(const int* __restrict__ src,
                                                    const int* __restrict__ dst,
                                                    const float* __restrict__ X,
                                                    const float* __restrict__ W) {
    if (blockIdx.x < GRIDG) {
        gemm_core(blockIdx.x, X, W, g_bufA, NN);
    } else {
        int e = (blockIdx.x - GRIDG) * 256 + threadIdx.x;
        if (e < EE) {
            int d = dst[e];
            int pos = atomicAdd(&g_cursor[d], 1);
            g_csrc[pos] = src[e];
        }
    }
}

__global__ void __launch_bounds__(256) k_gemm2(const float* __restrict__ W) {
    gemm_core(blockIdx.x, g_bufB, W, g_bufA, NN);
}

// ================= aggregation: warp per node, ILP-4 gathers, no atomics ======
// bufA holds Hs = (XW)*dinv.  res = dinv[i] * ( Hs[i] + sum_{s->i} Hs[s] )
__device__ __forceinline__ float4 agg_node(int i, int lane) {
    const float4* H4 = (const float4*)g_bufA;
    float di = g_dinv[i];

    float4 acc = H4[(size_t)i * 32 + lane];   // self term (pre-scaled)
    int j  = g_rows[i];
    int en = j + g_dege[i];
    for (; j + 4 <= en; j += 4) {
        int s0 = __ldg(&g_csrc[j]);
        int s1 = __ldg(&g_csrc[j + 1]);
        int s2 = __ldg(&g_csrc[j + 2]);
        int s3 = __ldg(&g_csrc[j + 3]);
        float4 v0 = H4[(size_t)s0 * 32 + lane];
        float4 v1 = H4[(size_t)s1 * 32 + lane];
        float4 v2 = H4[(size_t)s2 * 32 + lane];
        float4 v3 = H4[(size_t)s3 * 32 + lane];
        acc.x += v0.x + v1.x + v2.x + v3.x;
        acc.y += v0.y + v1.y + v2.y + v3.y;
        acc.z += v0.z + v1.z + v2.z + v3.z;
        acc.w += v0.w + v1.w + v2.w + v3.w;
    }
    for (; j < en; j++) {
        int s = __ldg(&g_csrc[j]);
        float4 v = H4[(size_t)s * 32 + lane];
        acc.x += v.x; acc.y += v.y; acc.z += v.z; acc.w += v.w;
    }
    acc.x *= di; acc.y *= di; acc.z *= di; acc.w *= di;
    return acc;
}

// layer-1 epilogue: relu(acc + b1) -> g_bufB
__global__ void k_agg_relu(const float* __restrict__ b) {
    int gid  = blockIdx.x * blockDim.x + threadIdx.x;
    int i    = gid >> 5;
    if (i >= NN) return;
    int lane = gid & 31;

    float4 acc = agg_node(i, lane);
    float4 bb = ((const float4*)b)[lane];
    acc.x = fmaxf(acc.x + bb.x, 0.f);
    acc.y = fmaxf(acc.y + bb.y, 0.f);
    acc.z = fmaxf(acc.z + bb.z, 0.f);
    acc.w = fmaxf(acc.w + bb.w, 0.f);
    ((float4*)(g_bufB + (size_t)i * DD))[lane] = acc;
}

// layer-2 epilogue: relu(acc + b2), then two head dot-products -> out
__global__ void k_agg_heads(const float* __restrict__ b2,
                            const float* __restrict__ Wt, const float* __restrict__ bt,
                            const float* __restrict__ We, const float* __restrict__ be,
                            float* __restrict__ out) {
    int gid  = blockIdx.x * blockDim.x + threadIdx.x;
    int i    = gid >> 5;
    if (i >= NN) return;
    int lane = gid & 31;

    float4 acc = agg_node(i, lane);
    float4 bb = ((const float4*)b2)[lane];
    acc.x = fmaxf(acc.x + bb.x, 0.f);
    acc.y = fmaxf(acc.y + bb.y, 0.f);
    acc.z = fmaxf(acc.z + bb.z, 0.f);
    acc.w = fmaxf(acc.w + bb.w, 0.f);

    float4 wt = ((const float4*)Wt)[lane];
    float4 we = ((const float4*)We)[lane];
    float stv = acc.x * wt.x + acc.y * wt.y + acc.z * wt.z + acc.w * wt.w;
    float evv = acc.x * we.x + acc.y * we.y + acc.z * we.z + acc.w * we.w;
#pragma unroll
    for (int off = 16; off > 0; off >>= 1) {
        stv += __shfl_xor_sync(0xFFFFFFFF, stv, off);
        evv += __shfl_xor_sync(0xFFFFFFFF, evv, off);
    }
    if (lane == 0) {
        out[i]      = stv + bt[0];
        out[NN + i] = evv + be[0];
    }
}

// ================= launch =================
extern "C" void kernel_launch(void* const* d_in, const int* in_sizes, int n_in,
                              void* d_out, int out_size) {
    const float* x  = (const float*)d_in[0];
    const int*   ei = (const int*)  d_in[1];
    const float* W1 = (const float*)d_in[2];
    const float* b1 = (const float*)d_in[3];
    const float* W2 = (const float*)d_in[4];
    const float* b2 = (const float*)d_in[5];
    const float* Wt = (const float*)d_in[6];
    const float* bt = (const float*)d_in[7];
    const float* We = (const float*)d_in[8];
    const float* be = (const float*)d_in[9];
    float* out = (float*)d_out;

    const int* src = ei;        // edge_index[0]
    const int* dst = ei + EE;   // edge_index[1]

    const int T = 256;
    int gridN   = (NN + T - 1) / T;      // 196
    int gridE   = (EE + T - 1) / T;      // 3125
    int gridN32 = (NN * 32 + T - 1) / T; // 6250

    // CSR build (scan split) + normalization
    k_zero  <<<gridN, T>>>();
    k_count <<<gridE, T>>>(dst);
    k_scanA <<<NBLK, 256>>>();
    k_scanC <<<NBLK, 256>>>();

    // layer 1: CSR fill runs concurrently with gemm1 inside one kernel
    k_fill_gemm1<<<GRIDG + GRIDE, T>>>(src, dst, x, W1);
    k_agg_relu  <<<gridN32, T>>>(b1);

    // layer 2
    k_gemm2     <<<GRIDG, T>>>(W2);
    k_agg_heads <<<gridN32, T>>>(b2, Wt, bt, We, be, out);
}